// round 9
// baseline (speedup 1.0000x reference)
#include <cuda_runtime.h>
#include <cuda_fp16.h>
#include <cstdint>

#define N1C 40000
#define N2C 8000
#define E1C 1000000
#define E2C 200000
#define DIN 256
#define HID 256

// ---------------- scratch (device globals: no allocation allowed) ----------
__device__ __align__(16) float g_h1[(size_t)N1C * HID];
__device__ __align__(16) __half g_A[(size_t)N1C * 512];     // [row][k]: 0-255 mean, 256-511 root
__device__ __align__(16) __half g_Bhi[2 * 512 * 256];
__device__ __align__(16) __half g_Blo[2 * 512 * 256];
__device__ __align__(16) int g_hist[N1C + N2C];             // zero-init; scan re-zeros
__device__ int g_off1[N1C + 1];
__device__ int g_cur1[N1C];
__device__ int g_off2[N2C + 1];
__device__ int g_cur2[N2C];
__device__ int g_ss1[E1C];
__device__ int g_ss2[E2C];

// ---------------- helpers ----------------------------------------------------
__device__ __forceinline__ uint32_t smem_u32(const void* p) {
    uint32_t a;
    asm("{ .reg .u64 t; cvta.to.shared.u64 t, %1; cvt.u32.u64 %0, t; }" : "=r"(a) : "l"(p));
    return a;
}
__device__ __forceinline__ void cp16p(uint32_t dst, const void* src, bool pred) {
    int n = pred ? 16 : 0;
    asm volatile("cp.async.cg.shared.global [%0], [%1], 16, %2;" :: "r"(dst), "l"(src), "r"(n));
}
#define CP_COMMIT() asm volatile("cp.async.commit_group;" ::: "memory")
__device__ __forceinline__ void ldsm4(uint32_t& r0, uint32_t& r1, uint32_t& r2, uint32_t& r3, uint32_t a) {
    asm volatile("ldmatrix.sync.aligned.m8n8.x4.shared.b16 {%0,%1,%2,%3}, [%4];"
                 : "=r"(r0), "=r"(r1), "=r"(r2), "=r"(r3) : "r"(a));
}
__device__ __forceinline__ void ldsm4t(uint32_t& r0, uint32_t& r1, uint32_t& r2, uint32_t& r3, uint32_t a) {
    asm volatile("ldmatrix.sync.aligned.m8n8.x4.trans.shared.b16 {%0,%1,%2,%3}, [%4];"
                 : "=r"(r0), "=r"(r1), "=r"(r2), "=r"(r3) : "r"(a));
}
__device__ __forceinline__ void mma16816h(float* c, const uint32_t* a, const uint32_t* b) {
    asm volatile("mma.sync.aligned.m16n8k16.row.col.f32.f16.f16.f32 "
                 "{%0,%1,%2,%3}, {%4,%5,%6,%7}, {%8,%9}, {%0,%1,%2,%3};"
                 : "+f"(c[0]), "+f"(c[1]), "+f"(c[2]), "+f"(c[3])
                 : "r"(a[0]), "r"(a[1]), "r"(a[2]), "r"(a[3]), "r"(b[0]), "r"(b[1]));
}
__device__ __forceinline__ uint32_t f2h2(float a, float b) {
    __half2 h = __floats2half2_rn(a, b);
    return *reinterpret_cast<uint32_t*>(&h);
}
__device__ __forceinline__ void acc4(float4& A, const float4& v) {
    A.x += v.x; A.y += v.y; A.z += v.z; A.w += v.w;
}

// ---------------- hist (+ optional fused B pack) --------------------------------
// blocks [0, histBlocks): 4-way histogram of dst
// blocks [histBlocks, ...): pack weights into fp16 hi/lo planes (layer-1 call only)
__global__ void hist_pack(const int* __restrict__ dst, int E, int* __restrict__ hist,
                          int histBlocks,
                          const float* __restrict__ Wl1, const float* __restrict__ Wr1,
                          const float* __restrict__ Wl2, const float* __restrict__ Wr2,
                          __half* __restrict__ Bhi, __half* __restrict__ Blo) {
    if ((int)blockIdx.x < histBlocks) {
        int i = (blockIdx.x * blockDim.x + threadIdx.x) * 4;
        if (i + 4 <= E) {
            int4 d = __ldg(reinterpret_cast<const int4*>(dst + i));
            atomicAdd(hist + d.x, 1);
            atomicAdd(hist + d.y, 1);
            atomicAdd(hist + d.z, 1);
            atomicAdd(hist + d.w, 1);
        } else {
            for (int j = i; j < E; j++) atomicAdd(hist + __ldg(dst + j), 1);
        }
    } else {
        int idx = (blockIdx.x - histBlocks) * blockDim.x + threadIdx.x;  // < 2*512*64
        int l = idx >> 15;
        int k = (idx >> 6) & 511;
        int col = (idx & 63) * 4;
        const float* W = (l == 0) ? ((k < 256) ? Wl1 : Wr1) : ((k < 256) ? Wl2 : Wr2);
        float4 v = __ldg(reinterpret_cast<const float4*>(W + (size_t)(k & 255) * 256 + col));
        __half h0 = __float2half_rn(v.x), h1 = __float2half_rn(v.y);
        __half h2 = __float2half_rn(v.z), h3 = __float2half_rn(v.w);
        float l0 = v.x - __half2float(h0), l1 = v.y - __half2float(h1);
        float l2 = v.z - __half2float(h2), l3 = v.w - __half2float(h3);
        size_t o = ((size_t)l * 512 + k) * 256 + col;
        *reinterpret_cast<uint2*>(Bhi + o) = make_uint2(f2h2(__half2float(h0), __half2float(h1)),
                                                        f2h2(__half2float(h2), __half2float(h3)));
        *reinterpret_cast<uint2*>(Blo + o) = make_uint2(f2h2(l0, l1), f2h2(l2, l3));
    }
}

// single-block scan; also re-zeros hist for the next graph replay
__global__ void scan_kernel(int* __restrict__ hist, int n,
                            int* __restrict__ off, int* __restrict__ cur) {
    __shared__ int part[1024];
    int t = threadIdx.x;
    int chunk = (n + 1023) >> 10;
    int b = t * chunk;
    int s = 0;
    for (int i = 0; i < chunk; i++) if (b + i < n) s += hist[b + i];
    part[t] = s;
    __syncthreads();
#pragma unroll
    for (int d = 1; d < 1024; d <<= 1) {
        int v = (t >= d) ? part[t - d] : 0;
        __syncthreads();
        part[t] += v;
        __syncthreads();
    }
    int run = (t ? part[t - 1] : 0);
    for (int i = 0; i < chunk; i++) {
        int idx = b + i;
        if (idx < n) {
            int h = hist[idx];
            hist[idx] = 0;           // reset for next replay
            off[idx] = run; cur[idx] = run; run += h;
        }
    }
    if (t == 1023) off[n] = part[1023];
}

__global__ void reorder_kernel(const int* __restrict__ src, const int* __restrict__ dst,
                               int E, int* __restrict__ cur, int* __restrict__ ssrc) {
    int i = (blockIdx.x * blockDim.x + threadIdx.x) * 4;
    if (i + 4 <= E) {
        int4 d = __ldg(reinterpret_cast<const int4*>(dst + i));
        int4 s = __ldg(reinterpret_cast<const int4*>(src + i));
        int p0 = atomicAdd(cur + d.x, 1);
        int p1 = atomicAdd(cur + d.y, 1);
        int p2 = atomicAdd(cur + d.z, 1);
        int p3 = atomicAdd(cur + d.w, 1);
        ssrc[p0] = s.x; ssrc[p1] = s.y; ssrc[p2] = s.z; ssrc[p3] = s.w;
    } else {
        for (int j = i; j < E; j++) {
            int pos = atomicAdd(cur + __ldg(dst + j), 1);
            ssrc[pos] = __ldg(src + j);
        }
    }
}

// ---------------- segmented gather-mean -> packed fp16 A operand ---------------
__global__ __launch_bounds__(256)
void agg_mean(const float* __restrict__ x, const float* __restrict__ xroot,
              const int* __restrict__ ssrc, const int* __restrict__ off,
              __half* __restrict__ A, int n_tgt) {
    int w = (blockIdx.x * blockDim.x + threadIdx.x) >> 5;
    if (w >= n_tgt) return;
    int lane = threadIdx.x & 31;
    int s0 = __ldg(off + w), s1 = __ldg(off + w + 1);

    float4 A0 = make_float4(0.f, 0.f, 0.f, 0.f);
    float4 A1 = make_float4(0.f, 0.f, 0.f, 0.f);
    int e = s0;
    for (; e + 4 <= s1; e += 4) {
        int sa = __ldg(ssrc + e), sb = __ldg(ssrc + e + 1);
        int sc = __ldg(ssrc + e + 2), sd = __ldg(ssrc + e + 3);
        const float4* pa = reinterpret_cast<const float4*>(x) + (size_t)sa * 64;
        const float4* pb = reinterpret_cast<const float4*>(x) + (size_t)sb * 64;
        const float4* pc = reinterpret_cast<const float4*>(x) + (size_t)sc * 64;
        const float4* pd = reinterpret_cast<const float4*>(x) + (size_t)sd * 64;
        float4 a0 = __ldg(pa + lane), a1 = __ldg(pa + lane + 32);
        float4 b0 = __ldg(pb + lane), b1 = __ldg(pb + lane + 32);
        float4 c0 = __ldg(pc + lane), c1 = __ldg(pc + lane + 32);
        float4 d0 = __ldg(pd + lane), d1 = __ldg(pd + lane + 32);
        acc4(A0, a0); acc4(A0, b0); acc4(A0, c0); acc4(A0, d0);
        acc4(A1, a1); acc4(A1, b1); acc4(A1, c1); acc4(A1, d1);
    }
    for (; e < s1; e++) {
        int sa = __ldg(ssrc + e);
        const float4* pa = reinterpret_cast<const float4*>(x) + (size_t)sa * 64;
        float4 a0 = __ldg(pa + lane), a1 = __ldg(pa + lane + 32);
        acc4(A0, a0); acc4(A1, a1);
    }
    float inv = 1.0f / fmaxf((float)(s1 - s0), 1.0f);
    A0.x *= inv; A0.y *= inv; A0.z *= inv; A0.w *= inv;
    A1.x *= inv; A1.y *= inv; A1.z *= inv; A1.w *= inv;

    const float4* px = reinterpret_cast<const float4*>(xroot) + (size_t)w * 64;
    float4 X0 = __ldg(px + lane), X1 = __ldg(px + lane + 32);

    __half* rp = A + (size_t)w * 512 + lane * 4;
    *reinterpret_cast<uint2*>(rp)       = make_uint2(f2h2(A0.x, A0.y), f2h2(A0.z, A0.w));
    *reinterpret_cast<uint2*>(rp + 128) = make_uint2(f2h2(A1.x, A1.y), f2h2(A1.z, A1.w));
    *reinterpret_cast<uint2*>(rp + 256) = make_uint2(f2h2(X0.x, X0.y), f2h2(X0.z, X0.w));
    *reinterpret_cast<uint2*>(rp + 384) = make_uint2(f2h2(X1.x, X1.y), f2h2(X1.z, X1.w));
}

// ---------------- fp16 2-combo GEMM, BM=128/BN=128, warp tile 32x64 ------------
#define FBM 128
#define FBN 128

__global__ __launch_bounds__(256, 2)
void gemm_fp16(const __half* __restrict__ A,
               const __half* __restrict__ Bhi, const __half* __restrict__ Blo,
               const float* __restrict__ bias, const float* __restrict__ alpha,
               float* __restrict__ out, int M) {
    extern __shared__ char smem[];
    uint32_t sb = smem_u32(smem);
    const uint32_t sA = sb;              // 2 x 16KB
    const uint32_t sB = sb + 32768u;     // 2 x 32KB (hi 16K + lo 16K)
    const int tid = threadIdx.x;
    const int wid = tid >> 5, lane = tid & 31;
    const int bm = blockIdx.x * FBM;
    const int bn = blockIdx.y * FBN;
    const int m0 = (wid & 3) * 32;
    const int n0 = (wid >> 2) * 64;

    float acc[2][8][4];
#pragma unroll
    for (int i = 0; i < 2; i++)
#pragma unroll
        for (int j = 0; j < 8; j++)
#pragma unroll
            for (int r = 0; r < 4; r++) acc[i][j][r] = 0.0f;

#define LD_AB(c, buf) do { \
        uint32_t _da = sA + (uint32_t)(buf) * 16384u; \
        _Pragma("unroll") \
        for (int i = 0; i < 4; i++) { \
            int row = (tid >> 3) + i * 32; \
            int seg = tid & 7; \
            int grow = bm + row; \
            uint32_t off = (((uint32_t)row * 128u + (uint32_t)seg * 16u) ^ (((uint32_t)row & 7u) << 4)); \
            cp16p(_da + off, A + (size_t)grow * 512 + (c) * 64 + seg * 8, grow < M); \
        } \
        uint32_t _dh = sB + (uint32_t)(buf) * 32768u; \
        uint32_t _dl = _dh + 16384u; \
        _Pragma("unroll") \
        for (int i = 0; i < 4; i++) { \
            int row = (tid >> 4) + i * 16; \
            int seg = tid & 15; \
            uint32_t off = (((uint32_t)row * 256u + (uint32_t)seg * 16u) ^ (((uint32_t)row & 7u) << 4)); \
            cp16p(_dh + off, Bhi + (size_t)((c) * 64 + row) * 256 + bn + seg * 8, true); \
            cp16p(_dl + off, Blo + (size_t)((c) * 64 + row) * 256 + bn + seg * 8, true); \
        } \
        CP_COMMIT(); \
    } while (0)

    LD_AB(0, 0);

#pragma unroll 1
    for (int c = 0; c < 8; c++) {
        const int buf = c & 1;
        if (c + 1 < 8) {
            LD_AB(c + 1, buf ^ 1);
            asm volatile("cp.async.wait_group 1;" ::: "memory");
        } else {
            asm volatile("cp.async.wait_group 0;" ::: "memory");
        }
        __syncthreads();

        const uint32_t ab = sA + (uint32_t)buf * 16384u;
        const uint32_t bhb = sB + (uint32_t)buf * 32768u;
        const uint32_t blb = bhb + 16384u;
#pragma unroll
        for (int ks = 0; ks < 4; ks++) {
            uint32_t a[2][4];
#pragma unroll
            for (int i = 0; i < 2; i++) {
                uint32_t mrow = (uint32_t)(m0 + i * 16 + (lane & 15));
                uint32_t kb = (uint32_t)(ks * 32 + (lane >> 4) * 16);
                uint32_t off = ((mrow * 128u + kb) ^ ((mrow & 7u) << 4));
                ldsm4(a[i][0], a[i][1], a[i][2], a[i][3], ab + off);
            }
            uint32_t bh[8][2], bl[8][2];
#pragma unroll
            for (int j2 = 0; j2 < 4; j2++) {
                uint32_t krow = (uint32_t)(ks * 16 + (lane & 15));
                uint32_t cb = (uint32_t)((n0 + j2 * 16 + (lane >> 4) * 8) * 2);
                uint32_t off = ((krow * 256u + cb) ^ ((krow & 7u) << 4));
                ldsm4t(bh[j2 * 2][0], bh[j2 * 2][1], bh[j2 * 2 + 1][0], bh[j2 * 2 + 1][1], bhb + off);
                ldsm4t(bl[j2 * 2][0], bl[j2 * 2][1], bl[j2 * 2 + 1][0], bl[j2 * 2 + 1][1], blb + off);
            }
#pragma unroll
            for (int i = 0; i < 2; i++)
#pragma unroll
                for (int j = 0; j < 8; j++) {
                    mma16816h(acc[i][j], a[i], bh[j]);
                    mma16816h(acc[i][j], a[i], bl[j]);
                }
        }
        __syncthreads();
    }

    // ---- epilogue: bias + PReLU + store ----
#pragma unroll
    for (int i = 0; i < 2; i++) {
        int r0 = bm + m0 + i * 16 + (lane >> 2);
#pragma unroll
        for (int j = 0; j < 8; j++) {
            int col = bn + n0 + j * 8 + (lane & 3) * 2;
            float2 bb = __ldg(reinterpret_cast<const float2*>(bias + col));
            float2 aa = __ldg(reinterpret_cast<const float2*>(alpha + col));
            if (r0 < M) {
                float v0 = acc[i][j][0] + bb.x;
                float v1 = acc[i][j][1] + bb.y;
                v0 = v0 > 0.f ? v0 : aa.x * v0;
                v1 = v1 > 0.f ? v1 : aa.y * v1;
                *reinterpret_cast<float2*>(out + (size_t)r0 * 256 + col) = make_float2(v0, v1);
            }
            if (r0 + 8 < M) {
                float v2 = acc[i][j][2] + bb.x;
                float v3 = acc[i][j][3] + bb.y;
                v2 = v2 > 0.f ? v2 : aa.x * v2;
                v3 = v3 > 0.f ? v3 : aa.y * v3;
                *reinterpret_cast<float2*>(out + (size_t)(r0 + 8) * 256 + col) = make_float2(v2, v3);
            }
        }
    }
#undef LD_AB
}

// ---------------- launch -------------------------------------------------------
extern "C" void kernel_launch(void* const* d_in, const int* in_sizes, int n_in,
                              void* d_out, int out_size) {
    const float* x    = (const float*)d_in[0];
    const int*   src1 = (const int*)d_in[1];
    const int*   dst1 = (const int*)d_in[2];
    const int*   src2 = (const int*)d_in[3];
    const int*   dst2 = (const int*)d_in[4];

    int iW = 5;
    while (iW < n_in && in_sizes[iW] != DIN * HID) iW++;
    const float* W_l1 = (const float*)d_in[iW + 0];
    const float* W_r1 = (const float*)d_in[iW + 1];
    const float* b1   = (const float*)d_in[iW + 2];
    const float* a1   = (const float*)d_in[iW + 3];
    const float* W_l2 = (const float*)d_in[iW + 4];
    const float* W_r2 = (const float*)d_in[iW + 5];
    const float* b2   = (const float*)d_in[iW + 6];
    const float* a2   = (const float*)d_in[iW + 7];

    const int E1 = in_sizes[1];
    const int E2 = in_sizes[3];

    float* h1;
    __half *A, *Bhi, *Blo;
    int *hist, *off1, *cur1, *off2, *cur2, *ss1, *ss2;
    cudaGetSymbolAddress((void**)&h1,   g_h1);
    cudaGetSymbolAddress((void**)&A,    g_A);
    cudaGetSymbolAddress((void**)&Bhi,  g_Bhi);
    cudaGetSymbolAddress((void**)&Blo,  g_Blo);
    cudaGetSymbolAddress((void**)&hist, g_hist);
    cudaGetSymbolAddress((void**)&off1, g_off1);
    cudaGetSymbolAddress((void**)&cur1, g_cur1);
    cudaGetSymbolAddress((void**)&off2, g_off2);
    cudaGetSymbolAddress((void**)&cur2, g_cur2);
    cudaGetSymbolAddress((void**)&ss1,  g_ss1);
    cudaGetSymbolAddress((void**)&ss2,  g_ss2);

    float* out = (float*)d_out;

    const int SMEM_GEMM = 2 * 16384 + 2 * 32768;   // 96KB
    cudaFuncSetAttribute(gemm_fp16, cudaFuncAttributeMaxDynamicSharedMemorySize, SMEM_GEMM);

    const int E4 = 256 * 4;
    const int hb1 = (E1 + E4 - 1) / E4;       // 977
    const int packBlocks = (2 * 512 * 64) / 256;  // 256

    // launch idx:
    hist_pack<<<hb1 + packBlocks, 256>>>(dst1, E1, hist, hb1,
                                         W_l1, W_r1, W_l2, W_r2, Bhi, Blo);     // 0
    scan_kernel<<<1, 1024>>>(hist, N1C, off1, cur1);                            // 1
    reorder_kernel<<<(E1 + E4 - 1) / E4, 256>>>(src1, dst1, E1, cur1, ss1);     // 2
    agg_mean<<<(N1C + 7) / 8, 256>>>(x, x, ss1, off1, A, N1C);                  // 3
    {
        dim3 grid((N1C + FBM - 1) / FBM, 2);                                    // 4 <- ncu
        gemm_fp16<<<grid, 256, SMEM_GEMM>>>(A, Bhi, Blo, b1, a1, h1, N1C);
    }

    // ---------------- layer 2 ----------------
    const int hb2 = (E2 + E4 - 1) / E4;
    hist_pack<<<hb2, 256>>>(dst2, E2, hist + N1C, hb2,
                            nullptr, nullptr, nullptr, nullptr, nullptr, nullptr);  // 5
    scan_kernel<<<1, 1024>>>(hist + N1C, N2C, off2, cur2);                      // 6
    reorder_kernel<<<(E2 + E4 - 1) / E4, 256>>>(src2, dst2, E2, cur2, ss2);     // 7
    agg_mean<<<(N2C + 7) / 8, 256>>>(h1, h1, ss2, off2, A, N2C);                // 8
    {
        dim3 grid((N2C + FBM - 1) / FBM, 2);                                    // 9
        gemm_fp16<<<grid, 256, SMEM_GEMM>>>(A, Bhi + 512 * 256, Blo + 512 * 256, b2, a2, out, N2C);
    }
}

// round 10
// speedup vs baseline: 1.0769x; 1.0769x over previous
#include <cuda_runtime.h>
#include <cuda_fp16.h>
#include <cstdint>

#define N1C 40000
#define N2C 8000
#define E1C 1000000
#define E2C 200000
#define DIN 256
#define HID 256

// ---------------- scratch (device globals: no allocation allowed) ----------
__device__ __align__(16) float g_h1[(size_t)N1C * HID];
__device__ __align__(16) __half g_A[(size_t)N1C * 512];     // [row][k]: 0-255 mean, 256-511 root
__device__ __align__(16) __half g_B[2 * 512 * 256];         // fp16 weights, [layer][k][n]
__device__ __align__(16) int g_hist[N1C + N2C];             // zero-init; scan re-zeros
__device__ int g_off1[N1C + 1];
__device__ int g_cur1[N1C];
__device__ int g_off2[N2C + 1];
__device__ int g_cur2[N2C];
__device__ int g_ss1[E1C];
__device__ int g_ss2[E2C];

// ---------------- helpers ----------------------------------------------------
__device__ __forceinline__ uint32_t smem_u32(const void* p) {
    uint32_t a;
    asm("{ .reg .u64 t; cvta.to.shared.u64 t, %1; cvt.u32.u64 %0, t; }" : "=r"(a) : "l"(p));
    return a;
}
__device__ __forceinline__ void cp16p(uint32_t dst, const void* src, bool pred) {
    int n = pred ? 16 : 0;
    asm volatile("cp.async.cg.shared.global [%0], [%1], 16, %2;" :: "r"(dst), "l"(src), "r"(n));
}
#define CP_COMMIT() asm volatile("cp.async.commit_group;" ::: "memory")
__device__ __forceinline__ void ldsm4(uint32_t& r0, uint32_t& r1, uint32_t& r2, uint32_t& r3, uint32_t a) {
    asm volatile("ldmatrix.sync.aligned.m8n8.x4.shared.b16 {%0,%1,%2,%3}, [%4];"
                 : "=r"(r0), "=r"(r1), "=r"(r2), "=r"(r3) : "r"(a));
}
__device__ __forceinline__ void ldsm4t(uint32_t& r0, uint32_t& r1, uint32_t& r2, uint32_t& r3, uint32_t a) {
    asm volatile("ldmatrix.sync.aligned.m8n8.x4.trans.shared.b16 {%0,%1,%2,%3}, [%4];"
                 : "=r"(r0), "=r"(r1), "=r"(r2), "=r"(r3) : "r"(a));
}
__device__ __forceinline__ void mma16816h(float* c, const uint32_t* a, const uint32_t* b) {
    asm volatile("mma.sync.aligned.m16n8k16.row.col.f32.f16.f16.f32 "
                 "{%0,%1,%2,%3}, {%4,%5,%6,%7}, {%8,%9}, {%0,%1,%2,%3};"
                 : "+f"(c[0]), "+f"(c[1]), "+f"(c[2]), "+f"(c[3])
                 : "r"(a[0]), "r"(a[1]), "r"(a[2]), "r"(a[3]), "r"(b[0]), "r"(b[1]));
}
__device__ __forceinline__ uint32_t f2h2(float a, float b) {
    __half2 h = __floats2half2_rn(a, b);
    return *reinterpret_cast<uint32_t*>(&h);
}
__device__ __forceinline__ void acc4(float4& A, const float4& v) {
    A.x += v.x; A.y += v.y; A.z += v.z; A.w += v.w;
}

// ---------------- hist (+ fused fp16 B pack on layer-1 call) --------------------
__global__ void hist_pack(const int* __restrict__ dst, int E, int* __restrict__ hist,
                          int histBlocks,
                          const float* __restrict__ Wl1, const float* __restrict__ Wr1,
                          const float* __restrict__ Wl2, const float* __restrict__ Wr2,
                          __half* __restrict__ B) {
    if ((int)blockIdx.x < histBlocks) {
        int i = (blockIdx.x * blockDim.x + threadIdx.x) * 4;
        if (i + 4 <= E) {
            int4 d = __ldg(reinterpret_cast<const int4*>(dst + i));
            atomicAdd(hist + d.x, 1);
            atomicAdd(hist + d.y, 1);
            atomicAdd(hist + d.z, 1);
            atomicAdd(hist + d.w, 1);
        } else {
            for (int j = i; j < E; j++) atomicAdd(hist + __ldg(dst + j), 1);
        }
    } else {
        int idx = (blockIdx.x - histBlocks) * blockDim.x + threadIdx.x;  // < 2*512*64
        int l = idx >> 15;
        int k = (idx >> 6) & 511;
        int col = (idx & 63) * 4;
        const float* W = (l == 0) ? ((k < 256) ? Wl1 : Wr1) : ((k < 256) ? Wl2 : Wr2);
        float4 v = __ldg(reinterpret_cast<const float4*>(W + (size_t)(k & 255) * 256 + col));
        size_t o = ((size_t)l * 512 + k) * 256 + col;
        *reinterpret_cast<uint2*>(B + o) = make_uint2(f2h2(v.x, v.y), f2h2(v.z, v.w));
    }
}

// single-block scan; re-zeros hist for the next graph replay
__global__ void scan_kernel(int* __restrict__ hist, int n,
                            int* __restrict__ off, int* __restrict__ cur) {
    __shared__ int part[1024];
    int t = threadIdx.x;
    int chunk = (n + 1023) >> 10;
    int b = t * chunk;
    int s = 0;
    for (int i = 0; i < chunk; i++) if (b + i < n) s += hist[b + i];
    part[t] = s;
    __syncthreads();
#pragma unroll
    for (int d = 1; d < 1024; d <<= 1) {
        int v = (t >= d) ? part[t - d] : 0;
        __syncthreads();
        part[t] += v;
        __syncthreads();
    }
    int run = (t ? part[t - 1] : 0);
    for (int i = 0; i < chunk; i++) {
        int idx = b + i;
        if (idx < n) {
            int h = hist[idx];
            hist[idx] = 0;
            off[idx] = run; cur[idx] = run; run += h;
        }
    }
    if (t == 1023) off[n] = part[1023];
}

__global__ void reorder_kernel(const int* __restrict__ src, const int* __restrict__ dst,
                               int E, int* __restrict__ cur, int* __restrict__ ssrc) {
    int i = (blockIdx.x * blockDim.x + threadIdx.x) * 4;
    if (i + 4 <= E) {
        int4 d = __ldg(reinterpret_cast<const int4*>(dst + i));
        int4 s = __ldg(reinterpret_cast<const int4*>(src + i));
        int p0 = atomicAdd(cur + d.x, 1);
        int p1 = atomicAdd(cur + d.y, 1);
        int p2 = atomicAdd(cur + d.z, 1);
        int p3 = atomicAdd(cur + d.w, 1);
        ssrc[p0] = s.x; ssrc[p1] = s.y; ssrc[p2] = s.z; ssrc[p3] = s.w;
    } else {
        for (int j = i; j < E; j++) {
            int pos = atomicAdd(cur + __ldg(dst + j), 1);
            ssrc[pos] = __ldg(src + j);
        }
    }
}

// ---------------- segmented gather-mean -> packed fp16 A operand ---------------
__global__ __launch_bounds__(256)
void agg_mean(const float* __restrict__ x, const float* __restrict__ xroot,
              const int* __restrict__ ssrc, const int* __restrict__ off,
              __half* __restrict__ A, int n_tgt) {
    int w = (blockIdx.x * blockDim.x + threadIdx.x) >> 5;
    if (w >= n_tgt) return;
    int lane = threadIdx.x & 31;
    int s0 = __ldg(off + w), s1 = __ldg(off + w + 1);

    float4 A0 = make_float4(0.f, 0.f, 0.f, 0.f);
    float4 A1 = make_float4(0.f, 0.f, 0.f, 0.f);
    int e = s0;
    for (; e + 4 <= s1; e += 4) {
        int sa = __ldg(ssrc + e), sb = __ldg(ssrc + e + 1);
        int sc = __ldg(ssrc + e + 2), sd = __ldg(ssrc + e + 3);
        const float4* pa = reinterpret_cast<const float4*>(x) + (size_t)sa * 64;
        const float4* pb = reinterpret_cast<const float4*>(x) + (size_t)sb * 64;
        const float4* pc = reinterpret_cast<const float4*>(x) + (size_t)sc * 64;
        const float4* pd = reinterpret_cast<const float4*>(x) + (size_t)sd * 64;
        float4 a0 = __ldg(pa + lane), a1 = __ldg(pa + lane + 32);
        float4 b0 = __ldg(pb + lane), b1 = __ldg(pb + lane + 32);
        float4 c0 = __ldg(pc + lane), c1 = __ldg(pc + lane + 32);
        float4 d0 = __ldg(pd + lane), d1 = __ldg(pd + lane + 32);
        acc4(A0, a0); acc4(A0, b0); acc4(A0, c0); acc4(A0, d0);
        acc4(A1, a1); acc4(A1, b1); acc4(A1, c1); acc4(A1, d1);
    }
    for (; e < s1; e++) {
        int sa = __ldg(ssrc + e);
        const float4* pa = reinterpret_cast<const float4*>(x) + (size_t)sa * 64;
        float4 a0 = __ldg(pa + lane), a1 = __ldg(pa + lane + 32);
        acc4(A0, a0); acc4(A1, a1);
    }
    float inv = 1.0f / fmaxf((float)(s1 - s0), 1.0f);
    A0.x *= inv; A0.y *= inv; A0.z *= inv; A0.w *= inv;
    A1.x *= inv; A1.y *= inv; A1.z *= inv; A1.w *= inv;

    const float4* px = reinterpret_cast<const float4*>(xroot) + (size_t)w * 64;
    float4 X0 = __ldg(px + lane), X1 = __ldg(px + lane + 32);

    __half* rp = A + (size_t)w * 512 + lane * 4;
    *reinterpret_cast<uint2*>(rp)       = make_uint2(f2h2(A0.x, A0.y), f2h2(A0.z, A0.w));
    *reinterpret_cast<uint2*>(rp + 128) = make_uint2(f2h2(A1.x, A1.y), f2h2(A1.z, A1.w));
    *reinterpret_cast<uint2*>(rp + 256) = make_uint2(f2h2(X0.x, X0.y), f2h2(X0.z, X0.w));
    *reinterpret_cast<uint2*>(rp + 384) = make_uint2(f2h2(X1.x, X1.y), f2h2(X1.z, X1.w));
}

// ---------------- fp16 single-combo GEMM + bias + PReLU ------------------------
// out[m,n] = prelu( sum_k A[m,k]*B[k,n] + bias[n], alpha[n] )
// BM=64, BN=128, BK=64, K=512 (8 chunks). A fp16, B fp16. 2-stage cp.async.
#define FBM 64
#define FBN 128

__global__ __launch_bounds__(256, 2)
void gemm_fp16(const __half* __restrict__ A, const __half* __restrict__ B,
               const float* __restrict__ bias, const float* __restrict__ alpha,
               float* __restrict__ out, int M) {
    extern __shared__ char smem[];
    uint32_t sb = smem_u32(smem);
    const uint32_t sA = sb;              // 2 x 8KB
    const uint32_t sB = sb + 16384u;     // 2 x 16KB
    const int tid = threadIdx.x;
    const int wid = tid >> 5, lane = tid & 31;
    const int bm = blockIdx.x * FBM;
    const int bn = blockIdx.y * FBN;
    const int m0 = (wid & 1) * 32;
    const int n0 = (wid >> 1) * 32;

    float acc[2][4][4];
#pragma unroll
    for (int i = 0; i < 2; i++)
#pragma unroll
        for (int j = 0; j < 4; j++)
#pragma unroll
            for (int r = 0; r < 4; r++) acc[i][j][r] = 0.0f;

    const int arow = tid >> 2, aq = tid & 3;
    const bool arok = (bm + arow) < M;

#define LD_AB(c, buf) do { \
        const __half* _sa = A + (size_t)(bm + arow) * 512 + (c) * 64 + aq * 8; \
        uint32_t _da = sA + (uint32_t)(buf) * 8192u; \
        uint32_t _o1 = (((uint32_t)arow * 128u + (uint32_t)aq * 16u) ^ (((uint32_t)arow & 7u) << 4)); \
        uint32_t _o2 = (((uint32_t)arow * 128u + (uint32_t)(aq + 4) * 16u) ^ (((uint32_t)arow & 7u) << 4)); \
        cp16p(_da + _o1, _sa, arok); \
        cp16p(_da + _o2, _sa + 32, arok); \
        const __half* _pb = B + (size_t)((c) * 64) * 256 + bn; \
        uint32_t _db = sB + (uint32_t)(buf) * 16384u; \
        _Pragma("unroll") \
        for (int i = 0; i < 4; i++) { \
            int row = (tid >> 4) + i * 16; \
            int seg = tid & 15; \
            uint32_t off = (((uint32_t)row * 256u + (uint32_t)seg * 16u) ^ (((uint32_t)row & 7u) << 4)); \
            cp16p(_db + off, _pb + (size_t)row * 256 + seg * 8, true); \
        } \
        CP_COMMIT(); \
    } while (0)

    LD_AB(0, 0);

#pragma unroll 1
    for (int c = 0; c < 8; c++) {
        const int buf = c & 1;
        if (c + 1 < 8) {
            LD_AB(c + 1, buf ^ 1);
            asm volatile("cp.async.wait_group 1;" ::: "memory");
        } else {
            asm volatile("cp.async.wait_group 0;" ::: "memory");
        }
        __syncthreads();

        const uint32_t ab = sA + (uint32_t)buf * 8192u;
        const uint32_t bb = sB + (uint32_t)buf * 16384u;
#pragma unroll
        for (int ks = 0; ks < 4; ks++) {
            uint32_t a[2][4];
#pragma unroll
            for (int i = 0; i < 2; i++) {
                uint32_t mrow = (uint32_t)(m0 + i * 16 + (lane & 15));
                uint32_t kb = (uint32_t)(ks * 32 + (lane >> 4) * 16);
                uint32_t off = ((mrow * 128u + kb) ^ ((mrow & 7u) << 4));
                ldsm4(a[i][0], a[i][1], a[i][2], a[i][3], ab + off);
            }
            uint32_t bh[4][2];
#pragma unroll
            for (int j2 = 0; j2 < 2; j2++) {
                uint32_t krow = (uint32_t)(ks * 16 + (lane & 15));
                uint32_t cb = (uint32_t)((n0 + j2 * 16 + (lane >> 4) * 8) * 2);
                uint32_t off = ((krow * 256u + cb) ^ ((krow & 7u) << 4));
                ldsm4t(bh[j2 * 2][0], bh[j2 * 2][1], bh[j2 * 2 + 1][0], bh[j2 * 2 + 1][1], bb + off);
            }
#pragma unroll
            for (int i = 0; i < 2; i++)
#pragma unroll
                for (int j = 0; j < 4; j++)
                    mma16816h(acc[i][j], a[i], bh[j]);
        }
        __syncthreads();
    }

    // ---- epilogue: bias + PReLU + store ----
#pragma unroll
    for (int i = 0; i < 2; i++) {
        int r0 = bm + m0 + i * 16 + (lane >> 2);
#pragma unroll
        for (int j = 0; j < 4; j++) {
            int col = bn + n0 + j * 8 + (lane & 3) * 2;
            float2 bb = __ldg(reinterpret_cast<const float2*>(bias + col));
            float2 aa = __ldg(reinterpret_cast<const float2*>(alpha + col));
            if (r0 < M) {
                float v0 = acc[i][j][0] + bb.x;
                float v1 = acc[i][j][1] + bb.y;
                v0 = v0 > 0.f ? v0 : aa.x * v0;
                v1 = v1 > 0.f ? v1 : aa.y * v1;
                *reinterpret_cast<float2*>(out + (size_t)r0 * 256 + col) = make_float2(v0, v1);
            }
            if (r0 + 8 < M) {
                float v2 = acc[i][j][2] + bb.x;
                float v3 = acc[i][j][3] + bb.y;
                v2 = v2 > 0.f ? v2 : aa.x * v2;
                v3 = v3 > 0.f ? v3 : aa.y * v3;
                *reinterpret_cast<float2*>(out + (size_t)(r0 + 8) * 256 + col) = make_float2(v2, v3);
            }
        }
    }
#undef LD_AB
}

// ---------------- launch -------------------------------------------------------
extern "C" void kernel_launch(void* const* d_in, const int* in_sizes, int n_in,
                              void* d_out, int out_size) {
    const float* x    = (const float*)d_in[0];
    const int*   src1 = (const int*)d_in[1];
    const int*   dst1 = (const int*)d_in[2];
    const int*   src2 = (const int*)d_in[3];
    const int*   dst2 = (const int*)d_in[4];

    int iW = 5;
    while (iW < n_in && in_sizes[iW] != DIN * HID) iW++;
    const float* W_l1 = (const float*)d_in[iW + 0];
    const float* W_r1 = (const float*)d_in[iW + 1];
    const float* b1   = (const float*)d_in[iW + 2];
    const float* a1   = (const float*)d_in[iW + 3];
    const float* W_l2 = (const float*)d_in[iW + 4];
    const float* W_r2 = (const float*)d_in[iW + 5];
    const float* b2   = (const float*)d_in[iW + 6];
    const float* a2   = (const float*)d_in[iW + 7];

    const int E1 = in_sizes[1];
    const int E2 = in_sizes[3];

    float* h1;
    __half *A, *B;
    int *hist, *off1, *cur1, *off2, *cur2, *ss1, *ss2;
    cudaGetSymbolAddress((void**)&h1,   g_h1);
    cudaGetSymbolAddress((void**)&A,    g_A);
    cudaGetSymbolAddress((void**)&B,    g_B);
    cudaGetSymbolAddress((void**)&hist, g_hist);
    cudaGetSymbolAddress((void**)&off1, g_off1);
    cudaGetSymbolAddress((void**)&cur1, g_cur1);
    cudaGetSymbolAddress((void**)&off2, g_off2);
    cudaGetSymbolAddress((void**)&cur2, g_cur2);
    cudaGetSymbolAddress((void**)&ss1,  g_ss1);
    cudaGetSymbolAddress((void**)&ss2,  g_ss2);

    float* out = (float*)d_out;

    const int SMEM_GEMM = 2 * 8192 + 2 * 16384;   // 48KB
    cudaFuncSetAttribute(gemm_fp16, cudaFuncAttributeMaxDynamicSharedMemorySize, SMEM_GEMM);

    const int E4 = 256 * 4;
    const int hb1 = (E1 + E4 - 1) / E4;
    const int packBlocks = (2 * 512 * 64) / 256;

    // ---------------- layer 1 ----------------
    hist_pack<<<hb1 + packBlocks, 256>>>(dst1, E1, hist, hb1,
                                         W_l1, W_r1, W_l2, W_r2, B);
    scan_kernel<<<1, 1024>>>(hist, N1C, off1, cur1);
    reorder_kernel<<<(E1 + E4 - 1) / E4, 256>>>(src1, dst1, E1, cur1, ss1);
    agg_mean<<<(N1C + 7) / 8, 256>>>(x, x, ss1, off1, A, N1C);
    {
        dim3 grid((N1C + FBM - 1) / FBM, 2);
        gemm_fp16<<<grid, 256, SMEM_GEMM>>>(A, B, b1, a1, h1, N1C);
    }

    // ---------------- layer 2 ----------------
    const int hb2 = (E2 + E4 - 1) / E4;
    hist_pack<<<hb2, 256>>>(dst2, E2, hist + N1C, hb2,
                            nullptr, nullptr, nullptr, nullptr, nullptr);
    scan_kernel<<<1, 1024>>>(hist + N1C, N2C, off2, cur2);
    reorder_kernel<<<(E2 + E4 - 1) / E4, 256>>>(src2, dst2, E2, cur2, ss2);
    agg_mean<<<(N2C + 7) / 8, 256>>>(h1, h1, ss2, off2, A, N2C);
    {
        dim3 grid((N2C + FBM - 1) / FBM, 2);
        gemm_fp16<<<grid, 256, SMEM_GEMM>>>(A, B + 512 * 256, b2, a2, out, N2C);
    }
}

// round 11
// speedup vs baseline: 1.2036x; 1.1176x over previous
#include <cuda_runtime.h>
#include <cuda_fp16.h>
#include <cstdint>

#define N1C 40000
#define N2C 8000
#define E1C 1000000
#define E2C 200000
#define DIN 256
#define HID 256
#define NXROWS 200000

// ---------------- scratch (device globals: no allocation allowed) ----------
__device__ __align__(16) __half g_xh[(size_t)NXROWS * DIN];   // fp16 copy of x (102MB, fits L2)
__device__ __align__(16) __half g_h1[(size_t)N1C * HID];      // layer-1 output, fp16
__device__ __align__(16) __half g_A[(size_t)N1C * 512];       // packed GEMM A operand
__device__ __align__(16) __half g_B[2 * 512 * 256];           // fp16 weights
__device__ __align__(16) int g_hist[N1C + N2C];               // zero-init; scan re-zeros
__device__ int g_off1[N1C + 1];
__device__ int g_cur1[N1C];
__device__ int g_off2[N2C + 1];
__device__ int g_cur2[N2C];
__device__ int g_ss1[E1C];
__device__ int g_ss2[E2C];

// ---------------- helpers ----------------------------------------------------
__device__ __forceinline__ uint32_t smem_u32(const void* p) {
    uint32_t a;
    asm("{ .reg .u64 t; cvta.to.shared.u64 t, %1; cvt.u32.u64 %0, t; }" : "=r"(a) : "l"(p));
    return a;
}
__device__ __forceinline__ void cp16p(uint32_t dst, const void* src, bool pred) {
    int n = pred ? 16 : 0;
    asm volatile("cp.async.cg.shared.global [%0], [%1], 16, %2;" :: "r"(dst), "l"(src), "r"(n));
}
#define CP_COMMIT() asm volatile("cp.async.commit_group;" ::: "memory")
__device__ __forceinline__ void ldsm4(uint32_t& r0, uint32_t& r1, uint32_t& r2, uint32_t& r3, uint32_t a) {
    asm volatile("ldmatrix.sync.aligned.m8n8.x4.shared.b16 {%0,%1,%2,%3}, [%4];"
                 : "=r"(r0), "=r"(r1), "=r"(r2), "=r"(r3) : "r"(a));
}
__device__ __forceinline__ void ldsm4t(uint32_t& r0, uint32_t& r1, uint32_t& r2, uint32_t& r3, uint32_t a) {
    asm volatile("ldmatrix.sync.aligned.m8n8.x4.trans.shared.b16 {%0,%1,%2,%3}, [%4];"
                 : "=r"(r0), "=r"(r1), "=r"(r2), "=r"(r3) : "r"(a));
}
__device__ __forceinline__ void mma16816h(float* c, const uint32_t* a, const uint32_t* b) {
    asm volatile("mma.sync.aligned.m16n8k16.row.col.f32.f16.f16.f32 "
                 "{%0,%1,%2,%3}, {%4,%5,%6,%7}, {%8,%9}, {%0,%1,%2,%3};"
                 : "+f"(c[0]), "+f"(c[1]), "+f"(c[2]), "+f"(c[3])
                 : "r"(a[0]), "r"(a[1]), "r"(a[2]), "r"(a[3]), "r"(b[0]), "r"(b[1]));
}
__device__ __forceinline__ uint32_t f2h2(float a, float b) {
    __half2 h = __floats2half2_rn(a, b);
    return *reinterpret_cast<uint32_t*>(&h);
}
__device__ __forceinline__ void addh2(float& a, float& b, uint32_t p) {
    __half2 h = *reinterpret_cast<__half2*>(&p);
    float2 f = __half22float2(h);
    a += f.x; b += f.y;
}

// ---------------- hist + fp16 B pack + fp16 x convert (grid-partitioned) -------
__global__ void hist_pack(const int* __restrict__ dst, int E, int* __restrict__ hist,
                          int histBlocks, int packBlocks,
                          const float* __restrict__ Wl1, const float* __restrict__ Wr1,
                          const float* __restrict__ Wl2, const float* __restrict__ Wr2,
                          __half* __restrict__ B,
                          const float* __restrict__ x, __half* __restrict__ xh, int nX) {
    int bx = blockIdx.x;
    if (bx < histBlocks) {
        int i = (bx * blockDim.x + threadIdx.x) * 4;
        if (i + 4 <= E) {
            int4 d = __ldg(reinterpret_cast<const int4*>(dst + i));
            atomicAdd(hist + d.x, 1);
            atomicAdd(hist + d.y, 1);
            atomicAdd(hist + d.z, 1);
            atomicAdd(hist + d.w, 1);
        } else {
            for (int j = i; j < E; j++) atomicAdd(hist + __ldg(dst + j), 1);
        }
    } else if (bx < histBlocks + packBlocks) {
        int idx = (bx - histBlocks) * blockDim.x + threadIdx.x;  // < 2*512*64
        int l = idx >> 15;
        int k = (idx >> 6) & 511;
        int col = (idx & 63) * 4;
        const float* W = (l == 0) ? ((k < 256) ? Wl1 : Wr1) : ((k < 256) ? Wl2 : Wr2);
        float4 v = __ldg(reinterpret_cast<const float4*>(W + (size_t)(k & 255) * 256 + col));
        size_t o = ((size_t)l * 512 + k) * 256 + col;
        *reinterpret_cast<uint2*>(B + o) = make_uint2(f2h2(v.x, v.y), f2h2(v.z, v.w));
    } else {
        // convert x -> fp16, 8 floats per thread
        size_t base = ((size_t)(bx - histBlocks - packBlocks) * blockDim.x + threadIdx.x) * 8;
        if (base + 8 <= (size_t)nX) {
            float4 v0 = __ldg(reinterpret_cast<const float4*>(x + base));
            float4 v1 = __ldg(reinterpret_cast<const float4*>(x + base + 4));
            uint4 o;
            o.x = f2h2(v0.x, v0.y); o.y = f2h2(v0.z, v0.w);
            o.z = f2h2(v1.x, v1.y); o.w = f2h2(v1.z, v1.w);
            *reinterpret_cast<uint4*>(xh + base) = o;
        }
    }
}

// single-block scan; re-zeros hist for the next graph replay
__global__ void scan_kernel(int* __restrict__ hist, int n,
                            int* __restrict__ off, int* __restrict__ cur) {
    __shared__ int part[1024];
    int t = threadIdx.x;
    int chunk = (n + 1023) >> 10;
    int b = t * chunk;
    int s = 0;
    for (int i = 0; i < chunk; i++) if (b + i < n) s += hist[b + i];
    part[t] = s;
    __syncthreads();
#pragma unroll
    for (int d = 1; d < 1024; d <<= 1) {
        int v = (t >= d) ? part[t - d] : 0;
        __syncthreads();
        part[t] += v;
        __syncthreads();
    }
    int run = (t ? part[t - 1] : 0);
    for (int i = 0; i < chunk; i++) {
        int idx = b + i;
        if (idx < n) {
            int h = hist[idx];
            hist[idx] = 0;
            off[idx] = run; cur[idx] = run; run += h;
        }
    }
    if (t == 1023) off[n] = part[1023];
}

__global__ void reorder_kernel(const int* __restrict__ src, const int* __restrict__ dst,
                               int E, int* __restrict__ cur, int* __restrict__ ssrc) {
    int i = (blockIdx.x * blockDim.x + threadIdx.x) * 4;
    if (i + 4 <= E) {
        int4 d = __ldg(reinterpret_cast<const int4*>(dst + i));
        int4 s = __ldg(reinterpret_cast<const int4*>(src + i));
        int p0 = atomicAdd(cur + d.x, 1);
        int p1 = atomicAdd(cur + d.y, 1);
        int p2 = atomicAdd(cur + d.z, 1);
        int p3 = atomicAdd(cur + d.w, 1);
        ssrc[p0] = s.x; ssrc[p1] = s.y; ssrc[p2] = s.z; ssrc[p3] = s.w;
    } else {
        for (int j = i; j < E; j++) {
            int pos = atomicAdd(cur + __ldg(dst + j), 1);
            ssrc[pos] = __ldg(src + j);
        }
    }
}

// ---------------- segmented gather-mean over fp16 rows -> packed A -------------
// one warp per target row; each lane owns 8 contiguous halfs (one uint4 per row).
__global__ __launch_bounds__(256)
void agg_mean_h(const __half* __restrict__ xh, const __half* __restrict__ rooth,
                const int* __restrict__ ssrc, const int* __restrict__ off,
                __half* __restrict__ A, int n_tgt) {
    int w = (blockIdx.x * blockDim.x + threadIdx.x) >> 5;
    if (w >= n_tgt) return;
    int lane = threadIdx.x & 31;
    int s0 = __ldg(off + w), s1 = __ldg(off + w + 1);

    float a0 = 0.f, a1 = 0.f, a2 = 0.f, a3 = 0.f, a4 = 0.f, a5 = 0.f, a6 = 0.f, a7 = 0.f;
    int e = s0;
    for (; e + 8 <= s1; e += 8) {
        int si[8];
#pragma unroll
        for (int j = 0; j < 8; j++) si[j] = __ldg(ssrc + e + j);
        uint4 v[8];
#pragma unroll
        for (int j = 0; j < 8; j++)
            v[j] = __ldg(reinterpret_cast<const uint4*>(xh + (size_t)si[j] * 256) + lane);
#pragma unroll
        for (int j = 0; j < 8; j++) {
            addh2(a0, a1, v[j].x);
            addh2(a2, a3, v[j].y);
            addh2(a4, a5, v[j].z);
            addh2(a6, a7, v[j].w);
        }
    }
    for (; e < s1; e++) {
        int si = __ldg(ssrc + e);
        uint4 v = __ldg(reinterpret_cast<const uint4*>(xh + (size_t)si * 256) + lane);
        addh2(a0, a1, v.x);
        addh2(a2, a3, v.y);
        addh2(a4, a5, v.z);
        addh2(a6, a7, v.w);
    }
    float inv = 1.0f / fmaxf((float)(s1 - s0), 1.0f);
    uint4 om;
    om.x = f2h2(a0 * inv, a1 * inv);
    om.y = f2h2(a2 * inv, a3 * inv);
    om.z = f2h2(a4 * inv, a5 * inv);
    om.w = f2h2(a6 * inv, a7 * inv);

    uint4 orow = __ldg(reinterpret_cast<const uint4*>(rooth + (size_t)w * 256) + lane);

    uint4* ap = reinterpret_cast<uint4*>(A + (size_t)w * 512) + lane;
    ap[0]  = om;      // cols [0,256): mean
    ap[32] = orow;    // cols [256,512): root (already fp16)
}

// ---------------- fp16 single-combo GEMM + bias + PReLU ------------------------
#define FBM 64
#define FBN 128

template <typename OutT>
__global__ __launch_bounds__(256, 2)
void gemm_fp16(const __half* __restrict__ A, const __half* __restrict__ B,
               const float* __restrict__ bias, const float* __restrict__ alpha,
               OutT* __restrict__ out, int M) {
    extern __shared__ char smem[];
    uint32_t sb = smem_u32(smem);
    const uint32_t sA = sb;              // 2 x 8KB
    const uint32_t sB = sb + 16384u;     // 2 x 16KB
    const int tid = threadIdx.x;
    const int wid = tid >> 5, lane = tid & 31;
    const int bm = blockIdx.x * FBM;
    const int bn = blockIdx.y * FBN;
    const int m0 = (wid & 1) * 32;
    const int n0 = (wid >> 1) * 32;

    float acc[2][4][4];
#pragma unroll
    for (int i = 0; i < 2; i++)
#pragma unroll
        for (int j = 0; j < 4; j++)
#pragma unroll
            for (int r = 0; r < 4; r++) acc[i][j][r] = 0.0f;

    const int arow = tid >> 2, aq = tid & 3;
    const bool arok = (bm + arow) < M;

#define LD_AB(c, buf) do { \
        const __half* _sa = A + (size_t)(bm + arow) * 512 + (c) * 64 + aq * 8; \
        uint32_t _da = sA + (uint32_t)(buf) * 8192u; \
        uint32_t _o1 = (((uint32_t)arow * 128u + (uint32_t)aq * 16u) ^ (((uint32_t)arow & 7u) << 4)); \
        uint32_t _o2 = (((uint32_t)arow * 128u + (uint32_t)(aq + 4) * 16u) ^ (((uint32_t)arow & 7u) << 4)); \
        cp16p(_da + _o1, _sa, arok); \
        cp16p(_da + _o2, _sa + 32, arok); \
        const __half* _pb = B + (size_t)((c) * 64) * 256 + bn; \
        uint32_t _db = sB + (uint32_t)(buf) * 16384u; \
        _Pragma("unroll") \
        for (int i = 0; i < 4; i++) { \
            int row = (tid >> 4) + i * 16; \
            int seg = tid & 15; \
            uint32_t off = (((uint32_t)row * 256u + (uint32_t)seg * 16u) ^ (((uint32_t)row & 7u) << 4)); \
            cp16p(_db + off, _pb + (size_t)row * 256 + seg * 8, true); \
        } \
        CP_COMMIT(); \
    } while (0)

    LD_AB(0, 0);

#pragma unroll 1
    for (int c = 0; c < 8; c++) {
        const int buf = c & 1;
        if (c + 1 < 8) {
            LD_AB(c + 1, buf ^ 1);
            asm volatile("cp.async.wait_group 1;" ::: "memory");
        } else {
            asm volatile("cp.async.wait_group 0;" ::: "memory");
        }
        __syncthreads();

        const uint32_t ab = sA + (uint32_t)buf * 8192u;
        const uint32_t bb = sB + (uint32_t)buf * 16384u;
#pragma unroll
        for (int ks = 0; ks < 4; ks++) {
            uint32_t a[2][4];
#pragma unroll
            for (int i = 0; i < 2; i++) {
                uint32_t mrow = (uint32_t)(m0 + i * 16 + (lane & 15));
                uint32_t kb = (uint32_t)(ks * 32 + (lane >> 4) * 16);
                uint32_t off = ((mrow * 128u + kb) ^ ((mrow & 7u) << 4));
                ldsm4(a[i][0], a[i][1], a[i][2], a[i][3], ab + off);
            }
            uint32_t bh[4][2];
#pragma unroll
            for (int j2 = 0; j2 < 2; j2++) {
                uint32_t krow = (uint32_t)(ks * 16 + (lane & 15));
                uint32_t cb = (uint32_t)((n0 + j2 * 16 + (lane >> 4) * 8) * 2);
                uint32_t off = ((krow * 256u + cb) ^ ((krow & 7u) << 4));
                ldsm4t(bh[j2 * 2][0], bh[j2 * 2][1], bh[j2 * 2 + 1][0], bh[j2 * 2 + 1][1], bb + off);
            }
#pragma unroll
            for (int i = 0; i < 2; i++)
#pragma unroll
                for (int j = 0; j < 4; j++)
                    mma16816h(acc[i][j], a[i], bh[j]);
        }
        __syncthreads();
    }

    // ---- epilogue: bias + PReLU + store (fp32 or fp16 out) ----
#pragma unroll
    for (int i = 0; i < 2; i++) {
        int r0 = bm + m0 + i * 16 + (lane >> 2);
#pragma unroll
        for (int j = 0; j < 4; j++) {
            int col = bn + n0 + j * 8 + (lane & 3) * 2;
            float2 bb = __ldg(reinterpret_cast<const float2*>(bias + col));
            float2 aa = __ldg(reinterpret_cast<const float2*>(alpha + col));
#pragma unroll
            for (int h = 0; h < 2; h++) {
                int rr = r0 + h * 8;
                if (rr >= M) continue;
                float v0 = acc[i][j][h * 2 + 0] + bb.x;
                float v1 = acc[i][j][h * 2 + 1] + bb.y;
                v0 = v0 > 0.f ? v0 : aa.x * v0;
                v1 = v1 > 0.f ? v1 : aa.y * v1;
                if (sizeof(OutT) == 4) {
                    *reinterpret_cast<float2*>((float*)out + (size_t)rr * 256 + col) = make_float2(v0, v1);
                } else {
                    uint32_t p = f2h2(v0, v1);
                    *reinterpret_cast<uint32_t*>((__half*)out + (size_t)rr * 256 + col) = p;
                }
            }
        }
    }
#undef LD_AB
}

// ---------------- launch -------------------------------------------------------
extern "C" void kernel_launch(void* const* d_in, const int* in_sizes, int n_in,
                              void* d_out, int out_size) {
    const float* x    = (const float*)d_in[0];
    const int*   src1 = (const int*)d_in[1];
    const int*   dst1 = (const int*)d_in[2];
    const int*   src2 = (const int*)d_in[3];
    const int*   dst2 = (const int*)d_in[4];

    int iW = 5;
    while (iW < n_in && in_sizes[iW] != DIN * HID) iW++;
    const float* W_l1 = (const float*)d_in[iW + 0];
    const float* W_r1 = (const float*)d_in[iW + 1];
    const float* b1   = (const float*)d_in[iW + 2];
    const float* a1   = (const float*)d_in[iW + 3];
    const float* W_l2 = (const float*)d_in[iW + 4];
    const float* W_r2 = (const float*)d_in[iW + 5];
    const float* b2   = (const float*)d_in[iW + 6];
    const float* a2   = (const float*)d_in[iW + 7];

    const int E1 = in_sizes[1];
    const int E2 = in_sizes[3];
    const int nX = in_sizes[0];  // 200000*256

    __half *xh, *h1, *A, *B;
    int *hist, *off1, *cur1, *off2, *cur2, *ss1, *ss2;
    cudaGetSymbolAddress((void**)&xh,   g_xh);
    cudaGetSymbolAddress((void**)&h1,   g_h1);
    cudaGetSymbolAddress((void**)&A,    g_A);
    cudaGetSymbolAddress((void**)&B,    g_B);
    cudaGetSymbolAddress((void**)&hist, g_hist);
    cudaGetSymbolAddress((void**)&off1, g_off1);
    cudaGetSymbolAddress((void**)&cur1, g_cur1);
    cudaGetSymbolAddress((void**)&off2, g_off2);
    cudaGetSymbolAddress((void**)&cur2, g_cur2);
    cudaGetSymbolAddress((void**)&ss1,  g_ss1);
    cudaGetSymbolAddress((void**)&ss2,  g_ss2);

    float* out = (float*)d_out;

    const int SMEM_GEMM = 2 * 8192 + 2 * 16384;   // 48KB
    cudaFuncSetAttribute(gemm_fp16<__half>, cudaFuncAttributeMaxDynamicSharedMemorySize, SMEM_GEMM);
    cudaFuncSetAttribute(gemm_fp16<float>,  cudaFuncAttributeMaxDynamicSharedMemorySize, SMEM_GEMM);

    const int E4 = 256 * 4;
    const int hb1 = (E1 + E4 - 1) / E4;
    const int packBlocks = (2 * 512 * 64) / 256;            // 256
    const int convBlocks = (nX + 256 * 8 - 1) / (256 * 8);  // 25000

    // ---------------- layer 1 ----------------
    hist_pack<<<hb1 + packBlocks + convBlocks, 256>>>(dst1, E1, hist, hb1, packBlocks,
                                                      W_l1, W_r1, W_l2, W_r2, B, x, xh, nX);
    scan_kernel<<<1, 1024>>>(hist, N1C, off1, cur1);
    reorder_kernel<<<(E1 + E4 - 1) / E4, 256>>>(src1, dst1, E1, cur1, ss1);
    agg_mean_h<<<(N1C + 7) / 8, 256>>>(xh, xh, ss1, off1, A, N1C);
    {
        dim3 grid((N1C + FBM - 1) / FBM, 2);
        gemm_fp16<__half><<<grid, 256, SMEM_GEMM>>>(A, B, b1, a1, h1, N1C);
    }

    // ---------------- layer 2 ----------------
    const int hb2 = (E2 + E4 - 1) / E4;
    hist_pack<<<hb2, 256>>>(dst2, E2, hist + N1C, hb2, 0,
                            nullptr, nullptr, nullptr, nullptr, nullptr, nullptr, nullptr, 0);
    scan_kernel<<<1, 1024>>>(hist + N1C, N2C, off2, cur2);
    reorder_kernel<<<(E2 + E4 - 1) / E4, 256>>>(src2, dst2, E2, cur2, ss2);
    agg_mean_h<<<(N2C + 7) / 8, 256>>>(h1, h1, ss2, off2, A, N2C);
    {
        dim3 grid((N2C + FBM - 1) / FBM, 2);
        gemm_fp16<float><<<grid, 256, SMEM_GEMM>>>(A, B + 512 * 256, b2, a2, out, N2C);
    }
}

// round 12
// speedup vs baseline: 1.3147x; 1.0923x over previous
#include <cuda_runtime.h>
#include <cuda_fp16.h>
#include <cstdint>

#define N1C 40000
#define N2C 8000
#define E1C 1000000
#define E2C 200000
#define DIN 256
#define HID 256
#define NXROWS 200000

// ---------------- scratch (device globals: no allocation allowed) ----------
__device__ __align__(16) __half g_xh[(size_t)NXROWS * DIN];   // fp16 copy of x (102MB)
__device__ __align__(16) __half g_h1[(size_t)N1C * HID];      // layer-1 output, fp16
__device__ __align__(16) __half g_A[(size_t)N1C * 512];       // packed GEMM A operand
__device__ __align__(16) __half g_B[2 * 512 * 256];           // fp16 weights
__device__ __align__(16) int g_hist[N1C + N2C];               // zero-init; scan re-zeros
__device__ int g_off1[N1C + 1];
__device__ int g_cur1[N1C];
__device__ int g_off2[N2C + 1];
__device__ int g_cur2[N2C];
__device__ int g_ss1[E1C];
__device__ int g_ss2[E2C];

// ---------------- helpers ----------------------------------------------------
__device__ __forceinline__ uint32_t smem_u32(const void* p) {
    uint32_t a;
    asm("{ .reg .u64 t; cvta.to.shared.u64 t, %1; cvt.u32.u64 %0, t; }" : "=r"(a) : "l"(p));
    return a;
}
__device__ __forceinline__ void cp16p(uint32_t dst, const void* src, bool pred) {
    int n = pred ? 16 : 0;
    asm volatile("cp.async.cg.shared.global [%0], [%1], 16, %2;" :: "r"(dst), "l"(src), "r"(n));
}
#define CP_COMMIT() asm volatile("cp.async.commit_group;" ::: "memory")
__device__ __forceinline__ void ldsm4(uint32_t& r0, uint32_t& r1, uint32_t& r2, uint32_t& r3, uint32_t a) {
    asm volatile("ldmatrix.sync.aligned.m8n8.x4.shared.b16 {%0,%1,%2,%3}, [%4];"
                 : "=r"(r0), "=r"(r1), "=r"(r2), "=r"(r3) : "r"(a));
}
__device__ __forceinline__ void ldsm4t(uint32_t& r0, uint32_t& r1, uint32_t& r2, uint32_t& r3, uint32_t a) {
    asm volatile("ldmatrix.sync.aligned.m8n8.x4.trans.shared.b16 {%0,%1,%2,%3}, [%4];"
                 : "=r"(r0), "=r"(r1), "=r"(r2), "=r"(r3) : "r"(a));
}
__device__ __forceinline__ void mma16816h(float* c, const uint32_t* a, const uint32_t* b) {
    asm volatile("mma.sync.aligned.m16n8k16.row.col.f32.f16.f16.f32 "
                 "{%0,%1,%2,%3}, {%4,%5,%6,%7}, {%8,%9}, {%0,%1,%2,%3};"
                 : "+f"(c[0]), "+f"(c[1]), "+f"(c[2]), "+f"(c[3])
                 : "r"(a[0]), "r"(a[1]), "r"(a[2]), "r"(a[3]), "r"(b[0]), "r"(b[1]));
}
__device__ __forceinline__ uint32_t f2h2(float a, float b) {
    __half2 h = __floats2half2_rn(a, b);
    return *reinterpret_cast<uint32_t*>(&h);
}
__device__ __forceinline__ void addh2(float& a, float& b, uint32_t p) {
    __half2 h = *reinterpret_cast<__half2*>(&p);
    float2 f = __half22float2(h);
    a += f.x; b += f.y;
}

// ---------------- fused front kernel: hist1 | hist2 | B pack | x convert --------
__global__ void hist_all(const int* __restrict__ dst1, int E1c, int* __restrict__ hist1, int hb1,
                         const int* __restrict__ dst2, int E2c, int* __restrict__ hist2, int hb2,
                         int packBlocks,
                         const float* __restrict__ Wl1, const float* __restrict__ Wr1,
                         const float* __restrict__ Wl2, const float* __restrict__ Wr2,
                         __half* __restrict__ B,
                         const float* __restrict__ x, __half* __restrict__ xh, int nX) {
    int bx = blockIdx.x;
    if (bx < hb1 + hb2) {
        const int* dst = (bx < hb1) ? dst1 : dst2;
        int* hist = (bx < hb1) ? hist1 : hist2;
        int E = (bx < hb1) ? E1c : E2c;
        int lb = (bx < hb1) ? bx : bx - hb1;
        int i = (lb * blockDim.x + threadIdx.x) * 4;
        if (i + 4 <= E) {
            int4 d = __ldg(reinterpret_cast<const int4*>(dst + i));
            atomicAdd(hist + d.x, 1);
            atomicAdd(hist + d.y, 1);
            atomicAdd(hist + d.z, 1);
            atomicAdd(hist + d.w, 1);
        } else {
            for (int j = i; j < E; j++) atomicAdd(hist + __ldg(dst + j), 1);
        }
    } else if (bx < hb1 + hb2 + packBlocks) {
        int idx = (bx - hb1 - hb2) * blockDim.x + threadIdx.x;  // < 2*512*64
        int l = idx >> 15;
        int k = (idx >> 6) & 511;
        int col = (idx & 63) * 4;
        const float* W = (l == 0) ? ((k < 256) ? Wl1 : Wr1) : ((k < 256) ? Wl2 : Wr2);
        float4 v = __ldg(reinterpret_cast<const float4*>(W + (size_t)(k & 255) * 256 + col));
        size_t o = ((size_t)l * 512 + k) * 256 + col;
        *reinterpret_cast<uint2*>(B + o) = make_uint2(f2h2(v.x, v.y), f2h2(v.z, v.w));
    } else {
        size_t base = ((size_t)(bx - hb1 - hb2 - packBlocks) * blockDim.x + threadIdx.x) * 8;
        if (base + 8 <= (size_t)nX) {
            float4 v0 = __ldg(reinterpret_cast<const float4*>(x + base));
            float4 v1 = __ldg(reinterpret_cast<const float4*>(x + base + 4));
            uint4 o;
            o.x = f2h2(v0.x, v0.y); o.y = f2h2(v0.z, v0.w);
            o.z = f2h2(v1.x, v1.y); o.w = f2h2(v1.z, v1.w);
            *reinterpret_cast<uint4*>(xh + base) = o;
        }
    }
}

// ---------------- scan both layers in one launch (block 0: L1, block 1: L2) ----
__device__ void scan_dev(int* __restrict__ hist, int n,
                         int* __restrict__ off, int* __restrict__ cur) {
    __shared__ int part[1024];
    int t = threadIdx.x;
    int chunk = (n + 1023) >> 10;
    int b = t * chunk;
    int s = 0;
    for (int i = 0; i < chunk; i++) if (b + i < n) s += hist[b + i];
    part[t] = s;
    __syncthreads();
#pragma unroll
    for (int d = 1; d < 1024; d <<= 1) {
        int v = (t >= d) ? part[t - d] : 0;
        __syncthreads();
        part[t] += v;
        __syncthreads();
    }
    int run = (t ? part[t - 1] : 0);
    for (int i = 0; i < chunk; i++) {
        int idx = b + i;
        if (idx < n) {
            int h = hist[idx];
            hist[idx] = 0;
            off[idx] = run; cur[idx] = run; run += h;
        }
    }
    if (t == 1023) off[n] = part[1023];
}

__global__ void scan_both(int* __restrict__ hist,
                          int* __restrict__ off1, int* __restrict__ cur1,
                          int* __restrict__ off2, int* __restrict__ cur2) {
    if (blockIdx.x == 0) scan_dev(hist, N1C, off1, cur1);
    else                 scan_dev(hist + N1C, N2C, off2, cur2);
}

// ---------------- reorder both layers, grid-partitioned -------------------------
__device__ __forceinline__ void reorder_dev(const int* __restrict__ src, const int* __restrict__ dst,
                                            int E, int* __restrict__ cur, int* __restrict__ ssrc,
                                            int lb) {
    int i = (lb * (int)blockDim.x + (int)threadIdx.x) * 4;
    if (i + 4 <= E) {
        int4 d = __ldg(reinterpret_cast<const int4*>(dst + i));
        int4 s = __ldg(reinterpret_cast<const int4*>(src + i));
        int p0 = atomicAdd(cur + d.x, 1);
        int p1 = atomicAdd(cur + d.y, 1);
        int p2 = atomicAdd(cur + d.z, 1);
        int p3 = atomicAdd(cur + d.w, 1);
        ssrc[p0] = s.x; ssrc[p1] = s.y; ssrc[p2] = s.z; ssrc[p3] = s.w;
    } else {
        for (int j = i; j < E; j++) {
            int pos = atomicAdd(cur + __ldg(dst + j), 1);
            ssrc[pos] = __ldg(src + j);
        }
    }
}

__global__ void reorder_all(const int* __restrict__ src1, const int* __restrict__ dst1, int E1c,
                            int* __restrict__ cur1, int* __restrict__ ss1, int rb1,
                            const int* __restrict__ src2, const int* __restrict__ dst2, int E2c,
                            int* __restrict__ cur2, int* __restrict__ ss2) {
    int bx = blockIdx.x;
    if (bx < rb1) reorder_dev(src1, dst1, E1c, cur1, ss1, bx);
    else          reorder_dev(src2, dst2, E2c, cur2, ss2, bx - rb1);
}

// ---------------- segmented gather-mean over fp16 rows -> packed A -------------
__global__ __launch_bounds__(256)
void agg_mean_h(const __half* __restrict__ xh, const __half* __restrict__ rooth,
                const int* __restrict__ ssrc, const int* __restrict__ off,
                __half* __restrict__ A, int n_tgt) {
    int w = (blockIdx.x * blockDim.x + threadIdx.x) >> 5;
    if (w >= n_tgt) return;
    int lane = threadIdx.x & 31;
    int s0 = __ldg(off + w), s1 = __ldg(off + w + 1);

    float a0 = 0.f, a1 = 0.f, a2 = 0.f, a3 = 0.f, a4 = 0.f, a5 = 0.f, a6 = 0.f, a7 = 0.f;
    int e = s0;
    for (; e + 8 <= s1; e += 8) {
        int si[8];
#pragma unroll
        for (int j = 0; j < 8; j++) si[j] = __ldg(ssrc + e + j);
        uint4 v[8];
#pragma unroll
        for (int j = 0; j < 8; j++)
            v[j] = __ldg(reinterpret_cast<const uint4*>(xh + (size_t)si[j] * 256) + lane);
#pragma unroll
        for (int j = 0; j < 8; j++) {
            addh2(a0, a1, v[j].x);
            addh2(a2, a3, v[j].y);
            addh2(a4, a5, v[j].z);
            addh2(a6, a7, v[j].w);
        }
    }
    for (; e < s1; e++) {
        int si = __ldg(ssrc + e);
        uint4 v = __ldg(reinterpret_cast<const uint4*>(xh + (size_t)si * 256) + lane);
        addh2(a0, a1, v.x);
        addh2(a2, a3, v.y);
        addh2(a4, a5, v.z);
        addh2(a6, a7, v.w);
    }
    float inv = 1.0f / fmaxf((float)(s1 - s0), 1.0f);
    uint4 om;
    om.x = f2h2(a0 * inv, a1 * inv);
    om.y = f2h2(a2 * inv, a3 * inv);
    om.z = f2h2(a4 * inv, a5 * inv);
    om.w = f2h2(a6 * inv, a7 * inv);

    uint4 orow = __ldg(reinterpret_cast<const uint4*>(rooth + (size_t)w * 256) + lane);

    uint4* ap = reinterpret_cast<uint4*>(A + (size_t)w * 512) + lane;
    ap[0]  = om;
    ap[32] = orow;
}

// ---------------- fp16 GEMM, 3-stage cp.async, grid = (n-tiles, m-tiles) -------
#define FBM 64
#define FBN 128

template <typename OutT>
__global__ __launch_bounds__(256, 2)
void gemm_fp16(const __half* __restrict__ A, const __half* __restrict__ B,
               const float* __restrict__ bias, const float* __restrict__ alpha,
               OutT* __restrict__ out, int M) {
    extern __shared__ char smem[];
    uint32_t sb = smem_u32(smem);
    const uint32_t sA = sb;              // 3 x 8KB
    const uint32_t sB = sb + 24576u;     // 3 x 16KB
    const int tid = threadIdx.x;
    const int wid = tid >> 5, lane = tid & 31;
    const int bm = blockIdx.y * FBM;     // m-tiles on y (adjacent x share A via L2)
    const int bn = blockIdx.x * FBN;
    const int m0 = (wid & 1) * 32;
    const int n0 = (wid >> 1) * 32;

    float acc[2][4][4];
#pragma unroll
    for (int i = 0; i < 2; i++)
#pragma unroll
        for (int j = 0; j < 4; j++)
#pragma unroll
            for (int r = 0; r < 4; r++) acc[i][j][r] = 0.0f;

    const int arow = tid >> 2, aq = tid & 3;
    const bool arok = (bm + arow) < M;

#define LD_AB(c, buf) do { \
        const __half* _sa = A + (size_t)(bm + arow) * 512 + (c) * 64 + aq * 8; \
        uint32_t _da = sA + (uint32_t)(buf) * 8192u; \
        uint32_t _o1 = (((uint32_t)arow * 128u + (uint32_t)aq * 16u) ^ (((uint32_t)arow & 7u) << 4)); \
        uint32_t _o2 = (((uint32_t)arow * 128u + (uint32_t)(aq + 4) * 16u) ^ (((uint32_t)arow & 7u) << 4)); \
        cp16p(_da + _o1, _sa, arok); \
        cp16p(_da + _o2, _sa + 32, arok); \
        const __half* _pb = B + (size_t)((c) * 64) * 256 + bn; \
        uint32_t _db = sB + (uint32_t)(buf) * 16384u; \
        _Pragma("unroll") \
        for (int i = 0; i < 4; i++) { \
            int row = (tid >> 4) + i * 16; \
            int seg = tid & 15; \
            uint32_t off = (((uint32_t)row * 256u + (uint32_t)seg * 16u) ^ (((uint32_t)row & 7u) << 4)); \
            cp16p(_db + off, _pb + (size_t)row * 256 + seg * 8, true); \
        } \
        CP_COMMIT(); \
    } while (0)

    LD_AB(0, 0);
    LD_AB(1, 1);

#pragma unroll
    for (int c = 0; c < 8; c++) {
        const int buf = c % 3;
        if (c + 2 < 8) {
            LD_AB(c + 2, (c + 2) % 3);
            asm volatile("cp.async.wait_group 2;" ::: "memory");
        } else if (c + 1 < 8) {
            asm volatile("cp.async.wait_group 1;" ::: "memory");
        } else {
            asm volatile("cp.async.wait_group 0;" ::: "memory");
        }
        __syncthreads();

        const uint32_t ab = sA + (uint32_t)buf * 8192u;
        const uint32_t bb = sB + (uint32_t)buf * 16384u;
#pragma unroll
        for (int ks = 0; ks < 4; ks++) {
            uint32_t a[2][4];
#pragma unroll
            for (int i = 0; i < 2; i++) {
                uint32_t mrow = (uint32_t)(m0 + i * 16 + (lane & 15));
                uint32_t kb = (uint32_t)(ks * 32 + (lane >> 4) * 16);
                uint32_t off = ((mrow * 128u + kb) ^ ((mrow & 7u) << 4));
                ldsm4(a[i][0], a[i][1], a[i][2], a[i][3], ab + off);
            }
            uint32_t bh[4][2];
#pragma unroll
            for (int j2 = 0; j2 < 2; j2++) {
                uint32_t krow = (uint32_t)(ks * 16 + (lane & 15));
                uint32_t cb = (uint32_t)((n0 + j2 * 16 + (lane >> 4) * 8) * 2);
                uint32_t off = ((krow * 256u + cb) ^ ((krow & 7u) << 4));
                ldsm4t(bh[j2 * 2][0], bh[j2 * 2][1], bh[j2 * 2 + 1][0], bh[j2 * 2 + 1][1], bb + off);
            }
#pragma unroll
            for (int i = 0; i < 2; i++)
#pragma unroll
                for (int j = 0; j < 4; j++)
                    mma16816h(acc[i][j], a[i], bh[j]);
        }
        __syncthreads();
    }

    // ---- epilogue: bias + PReLU + store (fp32 or fp16 out) ----
#pragma unroll
    for (int i = 0; i < 2; i++) {
        int r0 = bm + m0 + i * 16 + (lane >> 2);
#pragma unroll
        for (int j = 0; j < 4; j++) {
            int col = bn + n0 + j * 8 + (lane & 3) * 2;
            float2 bb = __ldg(reinterpret_cast<const float2*>(bias + col));
            float2 aa = __ldg(reinterpret_cast<const float2*>(alpha + col));
#pragma unroll
            for (int h = 0; h < 2; h++) {
                int rr = r0 + h * 8;
                if (rr >= M) continue;
                float v0 = acc[i][j][h * 2 + 0] + bb.x;
                float v1 = acc[i][j][h * 2 + 1] + bb.y;
                v0 = v0 > 0.f ? v0 : aa.x * v0;
                v1 = v1 > 0.f ? v1 : aa.y * v1;
                if (sizeof(OutT) == 4) {
                    *reinterpret_cast<float2*>((float*)out + (size_t)rr * 256 + col) = make_float2(v0, v1);
                } else {
                    uint32_t p = f2h2(v0, v1);
                    *reinterpret_cast<uint32_t*>((__half*)out + (size_t)rr * 256 + col) = p;
                }
            }
        }
    }
#undef LD_AB
}

// ---------------- launch -------------------------------------------------------
extern "C" void kernel_launch(void* const* d_in, const int* in_sizes, int n_in,
                              void* d_out, int out_size) {
    const float* x    = (const float*)d_in[0];
    const int*   src1 = (const int*)d_in[1];
    const int*   dst1 = (const int*)d_in[2];
    const int*   src2 = (const int*)d_in[3];
    const int*   dst2 = (const int*)d_in[4];

    int iW = 5;
    while (iW < n_in && in_sizes[iW] != DIN * HID) iW++;
    const float* W_l1 = (const float*)d_in[iW + 0];
    const float* W_r1 = (const float*)d_in[iW + 1];
    const float* b1   = (const float*)d_in[iW + 2];
    const float* a1   = (const float*)d_in[iW + 3];
    const float* W_l2 = (const float*)d_in[iW + 4];
    const float* W_r2 = (const float*)d_in[iW + 5];
    const float* b2   = (const float*)d_in[iW + 6];
    const float* a2   = (const float*)d_in[iW + 7];

    const int E1 = in_sizes[1];
    const int E2 = in_sizes[3];
    const int nX = in_sizes[0];

    __half *xh, *h1, *A, *B;
    int *hist, *off1, *cur1, *off2, *cur2, *ss1, *ss2;
    cudaGetSymbolAddress((void**)&xh,   g_xh);
    cudaGetSymbolAddress((void**)&h1,   g_h1);
    cudaGetSymbolAddress((void**)&A,    g_A);
    cudaGetSymbolAddress((void**)&B,    g_B);
    cudaGetSymbolAddress((void**)&hist, g_hist);
    cudaGetSymbolAddress((void**)&off1, g_off1);
    cudaGetSymbolAddress((void**)&cur1, g_cur1);
    cudaGetSymbolAddress((void**)&off2, g_off2);
    cudaGetSymbolAddress((void**)&cur2, g_cur2);
    cudaGetSymbolAddress((void**)&ss1,  g_ss1);
    cudaGetSymbolAddress((void**)&ss2,  g_ss2);

    float* out = (float*)d_out;

    const int SMEM_GEMM = 3 * 8192 + 3 * 16384;   // 72KB
    cudaFuncSetAttribute(gemm_fp16<__half>, cudaFuncAttributeMaxDynamicSharedMemorySize, SMEM_GEMM);
    cudaFuncSetAttribute(gemm_fp16<float>,  cudaFuncAttributeMaxDynamicSharedMemorySize, SMEM_GEMM);

    const int E4 = 256 * 4;
    const int hb1 = (E1 + E4 - 1) / E4;
    const int hb2 = (E2 + E4 - 1) / E4;
    const int packBlocks = (2 * 512 * 64) / 256;
    const int convBlocks = (nX + 256 * 8 - 1) / (256 * 8);

    // 1: hist1 | hist2 | B pack | x->fp16 convert, one grid
    hist_all<<<hb1 + hb2 + packBlocks + convBlocks, 256>>>(
        dst1, E1, hist, hb1, dst2, E2, hist + N1C, hb2, packBlocks,
        W_l1, W_r1, W_l2, W_r2, B, x, xh, nX);
    // 2: both scans
    scan_both<<<2, 1024>>>(hist, off1, cur1, off2, cur2);
    // 3: both reorders
    reorder_all<<<hb1 + hb2, 256>>>(src1, dst1, E1, cur1, ss1, hb1,
                                    src2, dst2, E2, cur2, ss2);
    // 4: layer-1 gather
    agg_mean_h<<<(N1C + 7) / 8, 256>>>(xh, xh, ss1, off1, A, N1C);
    // 5: layer-1 GEMM (n-tiles fastest for A L2 reuse)
    {
        dim3 grid(HID / FBN, (N1C + FBM - 1) / FBM);
        gemm_fp16<__half><<<grid, 256, SMEM_GEMM>>>(A, B, b1, a1, h1, N1C);
    }
    // 6: layer-2 gather
    agg_mean_h<<<(N2C + 7) / 8, 256>>>(h1, h1, ss2, off2, A, N2C);
    // 7: layer-2 GEMM
    {
        dim3 grid(HID / FBN, (N2C + FBM - 1) / FBM);
        gemm_fp16<float><<<grid, 256, SMEM_GEMM>>>(A, B + 512 * 256, b2, a2, out, N2C);
    }
}